// round 16
// baseline (speedup 1.0000x reference)
#include <cuda_runtime.h>
#include <cuda_bf16.h>
#include <cuda_fp16.h>
#include <math.h>
#include <stdint.h>

// ---------------------------------------------------------------------------
// SpatialModel: 3-layer GATConv on two graphs (N=50000, E=800000), mean pool,
// MLP head -> [1,3] logits.
//
// R16: agg per-edge scalar work de-duplicated (lane-parallel exp + shfl
// broadcast; 4x less MUFU, 8x fewer hs LDGs), edge records packed to 4B
// (src:16 | col:fp16). Otherwise R15: fp16 MMA GEMM (A exact, W hi+lo),
// fp16 h/x payloads, fused mean-pool layer 2, two-stream pipeline.
// ---------------------------------------------------------------------------

#define MAX_N 50000
#define MAX_E 800000
#define TILE 512

__device__ __align__(16) __half g_hh[2][MAX_N * 128];
__device__ __align__(16) __half g_xh[2][MAX_N * 128];
__device__ float g_hs[2][MAX_N];
__device__ float g_hd[2][MAX_N];
__device__ int   g_deg[2][MAX_N];
__device__ int   g_offs[2][MAX_N + 1];
__device__ int   g_cursor[2][MAX_N];
__device__ __align__(16) uint32_t g_csre[2][MAX_E];   // src:16 | col(fp16):16
__device__ int   g_tsum[2][128];
__device__ float g_c[3];
__device__ unsigned g_maxhs[6];
__device__ float g_gvec[128];
__device__ __align__(16) __half g_wfh[2][128 * 128];
__device__ __align__(16) __half g_wfl[2][128 * 128];

// ---------------------------------------------------------------------------
__device__ __forceinline__ uint32_t smem_u32(const void* p) {
    uint32_t a;
    asm("{ .reg .u64 t; cvta.to.shared.u64 t, %1; cvt.u32.u64 %0, t; }"
        : "=r"(a) : "l"(p));
    return a;
}
__device__ __forceinline__ unsigned fkey(float f) {
    int i = __float_as_int(f);
    return i >= 0 ? ((unsigned)i | 0x80000000u) : ~(unsigned)i;
}
__device__ __forceinline__ float funkey(unsigned k) {
    return (k & 0x80000000u) ? __int_as_float((int)(k & 0x7FFFFFFFu))
                             : __int_as_float((int)~k);
}
__device__ __forceinline__ float pkcol(uint32_t pk) {
    return __half2float(__ushort_as_half((unsigned short)(pk >> 16)));
}
#define LDSM_X4(r0, r1, r2, r3, addr)                                          \
    asm volatile("ldmatrix.sync.aligned.m8n8.x4.shared.b16 {%0,%1,%2,%3}, [%4];" \
                 : "=r"(r0), "=r"(r1), "=r"(r2), "=r"(r3) : "r"(addr))
#define LDSM_X4_T(r0, r1, r2, r3, addr)                                        \
    asm volatile("ldmatrix.sync.aligned.m8n8.x4.trans.shared.b16 {%0,%1,%2,%3}, [%4];" \
                 : "=r"(r0), "=r"(r1), "=r"(r2), "=r"(r3) : "r"(addr))
__device__ __forceinline__ void mma_f16(float* c, uint32_t a0, uint32_t a1,
                                        uint32_t a2, uint32_t a3,
                                        uint32_t b0, uint32_t b1) {
    asm volatile(
        "mma.sync.aligned.m16n8k16.row.col.f32.f16.f16.f32 "
        "{%0,%1,%2,%3}, {%4,%5,%6,%7}, {%8,%9}, {%0,%1,%2,%3};"
        : "+f"(c[0]), "+f"(c[1]), "+f"(c[2]), "+f"(c[3])
        : "r"(a0), "r"(a1), "r"(a2), "r"(a3), "r"(b0), "r"(b1));
}

// ---------------------------------------------------------------------------
__global__ void build_deg_k(const int* __restrict__ ei0, const int* __restrict__ ei1,
                            int* deg, int E) {
    int i = (blockIdx.x * blockDim.x + threadIdx.x) * 2;
    if (i >= 2 * E) return;
    int g = (i >= E);
    int j = i - g * E;
    const int* dst = (g ? ei1 : ei0) + E;
    int d0 = dst[j];
    int d1 = dst[j + 1];
    atomicAdd(&deg[g * MAX_N + d0], 1);
    atomicAdd(&deg[g * MAX_N + d1], 1);
}

__global__ void scan1_k(const int* __restrict__ deg, int* tsum, int n, int nT) {
    __shared__ int sh[256];
    int bx = blockIdx.x, t = threadIdx.x;
    int g = (bx >= nT);
    int b = bx - g * nT;
    const int* dg = deg + g * MAX_N;
    int i0 = b * TILE;
    int s = 0;
    int i = i0 + t;        if (i < n) s += dg[i];
    i = i0 + 256 + t;      if (i < n) s += dg[i];
    sh[t] = s;
    __syncthreads();
    for (int o = 128; o; o >>= 1) { if (t < o) sh[t] += sh[t + o]; __syncthreads(); }
    if (t == 0) tsum[g * 128 + b] = sh[0];
}
__global__ void scan2_k(int* tsum, int nT) {
    __shared__ int sh[256];
    int t = threadIdx.x;
    int g = t >> 7, tl = t & 127;
    int v0 = (tl < nT) ? tsum[g * 128 + tl] : 0;
    sh[t] = v0;
    __syncthreads();
    for (int d = 1; d < 128; d <<= 1) {
        int v = (tl >= d) ? sh[t - d] : 0;
        __syncthreads();
        sh[t] += v;
        __syncthreads();
    }
    if (tl < nT) tsum[g * 128 + tl] = sh[t] - v0;
}
__global__ void scan3_k(const int* __restrict__ deg, const int* __restrict__ tsum,
                        int* offs, int* cursor, int n, int nT) {
    __shared__ int sh[TILE];
    int bx = blockIdx.x, t = threadIdx.x;
    int g = (bx >= nT);
    int b = bx - g * nT;
    const int* dg = deg + g * MAX_N;
    const int* ts = tsum + g * 128;
    int* of = offs + g * (MAX_N + 1);
    int* cu = cursor + g * MAX_N;
    int i = b * TILE + t;
    int d = (i < n) ? dg[i] : 0;
    sh[t] = d;
    __syncthreads();
    for (int o = 1; o < TILE; o <<= 1) {
        int v = (t >= o) ? sh[t - o] : 0;
        __syncthreads();
        sh[t] += v;
        __syncthreads();
    }
    if (i < n) {
        int base = ts[b];
        int off = base + sh[t] - d;
        of[i] = off;
        cu[i] = off;
        if (i == n - 1) of[n] = base + sh[t];
    }
}

__global__ void scatter_k(const int* __restrict__ ei0, const float* __restrict__ col0,
                          const int* __restrict__ ei1, const float* __restrict__ col1,
                          int* cursor, uint32_t* csre, int E) {
    int i = (blockIdx.x * blockDim.x + threadIdx.x) * 2;
    if (i >= 2 * E) return;
    int g = (i >= E);
    int j = i - g * E;
    const int* ei = g ? ei1 : ei0;
    const float* col = g ? col1 : col0;
    int* cur = cursor + g * MAX_N;
    uint32_t* cs = csre + (size_t)g * MAX_E;
    int s0 = ei[j], s1 = ei[j + 1];
    int d0 = ei[E + j], d1 = ei[E + j + 1];
    uint32_t k0 = (uint32_t)s0 |
                  ((uint32_t)__half_as_ushort(__float2half_rn(col[j])) << 16);
    uint32_t k1 = (uint32_t)s1 |
                  ((uint32_t)__half_as_ushort(__float2half_rn(col[j + 1])) << 16);
    int p0 = atomicAdd(&cur[d0], 1);
    int p1 = atomicAdd(&cur[d1], 1);
    cs[p0] = k0;
    cs[p1] = k1;
}

// ---------------------------------------------------------------------------
__global__ void wsplit_k(const float* __restrict__ W, __half* hi, __half* lo, int n) {
    int i = blockIdx.x * blockDim.x + threadIdx.x;
    if (i >= n) return;
    float v = W[i];
    __half h = __float2half_rn(v);
    hi[i] = h;
    lo[i] = __float2half_rn(v - __half2float(h));
}

__global__ void cscalar3_k(const float* __restrict__ We1, const float* __restrict__ ae1,
                           const float* __restrict__ We2, const float* __restrict__ ae2,
                           const float* __restrict__ We3, const float* __restrict__ ae3,
                           float* out) {
    int w = threadIdx.x >> 5, lane = threadIdx.x & 31;
    if (w >= 3) return;
    const float* We = (w == 0) ? We1 : (w == 1) ? We2 : We3;
    const float* ae = (w == 0) ? ae1 : (w == 1) ? ae2 : ae3;
    int C = (w == 2) ? 64 : 128;
    float s = 0.f;
    for (int k = lane; k < C; k += 32) s += We[k] * ae[k];
    #pragma unroll
    for (int o = 16; o; o >>= 1) s += __shfl_xor_sync(0xffffffffu, s, o);
    if (lane == 0) out[w] = s;
}

// ---------------------------------------------------------------------------
__global__ void __launch_bounds__(256)
gemm7_k(const float* __restrict__ x, const float* __restrict__ W,
        const float* __restrict__ asrc, const float* __restrict__ adst,
        __half* __restrict__ h, float* __restrict__ hs, float* __restrict__ hd,
        unsigned* __restrict__ gmax, int M) {
    __shared__ float Ws[7 * 128], As[128], Ad[128];
    __shared__ float wmax[8];
    int t = threadIdx.x;
    for (int i = t; i < 7 * 128; i += 256) Ws[i] = W[i];
    if (t < 128) { As[t] = asrc[t]; Ad[t] = adst[t]; }
    __syncthreads();
    int r = blockIdx.x * 8 + (t >> 5);
    bool active = (r < M);
    int lane = t & 31, c0 = lane * 4;
    float s = 0.f, d = 0.f;
    if (active) {
        float xv[7];
        #pragma unroll
        for (int k = 0; k < 7; k++) xv[k] = x[(size_t)r * 7 + k];
        float out[4];
        #pragma unroll
        for (int j = 0; j < 4; j++) {
            float acc = 0.f;
            #pragma unroll
            for (int k = 0; k < 7; k++) acc += xv[k] * Ws[k * 128 + c0 + j];
            out[j] = acc;
        }
        __half2 p0 = __floats2half2_rn(out[0], out[1]);
        __half2 p1 = __floats2half2_rn(out[2], out[3]);
        uint2 u = make_uint2(*(uint32_t*)&p0, *(uint32_t*)&p1);
        *(uint2*)(h + (size_t)r * 128 + c0) = u;
        s = out[0] * As[c0] + out[1] * As[c0 + 1] + out[2] * As[c0 + 2] + out[3] * As[c0 + 3];
        d = out[0] * Ad[c0] + out[1] * Ad[c0 + 1] + out[2] * Ad[c0 + 2] + out[3] * Ad[c0 + 3];
        #pragma unroll
        for (int o = 16; o; o >>= 1) {
            s += __shfl_xor_sync(0xffffffffu, s, o);
            d += __shfl_xor_sync(0xffffffffu, d, o);
        }
        if (lane == 0) { hs[r] = s; hd[r] = d; }
    }
    if (lane == 0) wmax[t >> 5] = active ? s : -3.4e38f;
    __syncthreads();
    if (t == 0) {
        float m = wmax[0];
        #pragma unroll
        for (int i = 1; i < 8; i++) m = fmaxf(m, wmax[i]);
        atomicMax(gmax, fkey(m));
    }
}

// ---------------------------------------------------------------------------
template <int CN>
__global__ void __launch_bounds__(256, 2)
gemm_mma_k(const __half* __restrict__ A, const __half* __restrict__ Bh,
           const __half* __restrict__ Bl,
           const float* __restrict__ asrc, const float* __restrict__ adst,
           __half* __restrict__ H, float* __restrict__ hs, float* __restrict__ hd,
           unsigned* __restrict__ gmax, int M) {
    extern __shared__ char smem[];
    constexpr int SA = 72;
    constexpr int SB = CN + 8;
    constexpr int AS = 0;
    constexpr int BH = 128 * SA * 2;
    constexpr int BL = BH + 64 * SB * 2;
    constexpr int NT = CN / 16;
    constexpr int NC8 = CN / 8;

    int tid = threadIdx.x, lane = tid & 31, warp = tid >> 5;
    const int rowBase = blockIdx.x * 128;

    __half* as = (__half*)(smem + AS);
    __half* bs_h = (__half*)(smem + BH);
    __half* bs_l = (__half*)(smem + BL);

    int wm = warp >> 1, wn = warp & 1;
    int m0 = wm * 32, n0 = wn * (CN / 2);

    float acc[2][NT][4];
    #pragma unroll
    for (int a = 0; a < 2; a++)
        #pragma unroll
        for (int b = 0; b < NT; b++)
            #pragma unroll
            for (int q = 0; q < 4; q++) acc[a][b][q] = 0.f;

    int lr = lane & 15, lc = lane >> 4;
    uint32_t sb_a = smem_u32(as);
    uint32_t sb_bh = smem_u32(bs_h), sb_bl = smem_u32(bs_l);

    #pragma unroll
    for (int kc = 0; kc < 128; kc += 64) {
        #pragma unroll
        for (int q = 0; q < 4; q++) {
            int i = q * 256 + tid;
            int r = i >> 3, c8 = i & 7;
            int gr = rowBase + r;
            uint4 u = make_uint4(0u, 0u, 0u, 0u);
            if (gr < M) u = *(const uint4*)(A + (size_t)gr * 128 + kc + c8 * 8);
            *(uint4*)(as + r * SA + c8 * 8) = u;
        }
        for (int i = tid; i < 64 * NC8; i += 256) {
            int r = i / NC8, c8 = i % NC8;
            int gi = (kc + r) * NC8 + c8;
            *(uint4*)(bs_h + r * SB + c8 * 8) = ((const uint4*)Bh)[gi];
            *(uint4*)(bs_l + r * SB + c8 * 8) = ((const uint4*)Bl)[gi];
        }
        __syncthreads();

        #pragma unroll
        for (int ks = 0; ks < 4; ks++) {
            int k0 = ks * 16;
            uint32_t af[2][4];
            #pragma unroll
            for (int mt = 0; mt < 2; mt++) {
                uint32_t off = ((m0 + mt * 16 + lr) * SA + k0 + lc * 8) * 2;
                LDSM_X4(af[mt][0], af[mt][1], af[mt][2], af[mt][3], sb_a + off);
            }
            #pragma unroll
            for (int n16 = 0; n16 < NT / 2; n16++) {
                uint32_t off = ((k0 + lr) * SB + n0 + n16 * 16 + lc * 8) * 2;
                uint32_t b0h, b1h, b2h, b3h, b0l, b1l, b2l, b3l;
                LDSM_X4_T(b0h, b1h, b2h, b3h, sb_bh + off);
                LDSM_X4_T(b0l, b1l, b2l, b3l, sb_bl + off);
                int nt0 = 2 * n16, nt1 = 2 * n16 + 1;
                #pragma unroll
                for (int mt = 0; mt < 2; mt++) {
                    mma_f16(acc[mt][nt0], af[mt][0], af[mt][1], af[mt][2], af[mt][3], b0h, b1h);
                    mma_f16(acc[mt][nt0], af[mt][0], af[mt][1], af[mt][2], af[mt][3], b0l, b1l);
                    mma_f16(acc[mt][nt1], af[mt][0], af[mt][1], af[mt][2], af[mt][3], b2h, b3h);
                    mma_f16(acc[mt][nt1], af[mt][0], af[mt][1], af[mt][2], af[mt][3], b2l, b3l);
                }
            }
        }
        __syncthreads();
    }

    int g = lane >> 2, tig = lane & 3;
    #pragma unroll
    for (int mt = 0; mt < 2; mt++) {
        int r0 = rowBase + m0 + mt * 16 + g;
        int r1 = r0 + 8;
        #pragma unroll
        for (int nt = 0; nt < NT; nt++) {
            int col = n0 + nt * 8 + tig * 2;
            if (r0 < M)
                *(__half2*)(H + (size_t)r0 * CN + col) =
                    __floats2half2_rn(acc[mt][nt][0], acc[mt][nt][1]);
            if (r1 < M)
                *(__half2*)(H + (size_t)r1 * CN + col) =
                    __floats2half2_rn(acc[mt][nt][2], acc[mt][nt][3]);
        }
    }

    float sd[2][2] = {}, dd[2][2] = {};
    #pragma unroll
    for (int mt = 0; mt < 2; mt++)
        #pragma unroll
        for (int nt = 0; nt < NT; nt++) {
            int col = n0 + nt * 8 + tig * 2;
            float a0 = __ldg(asrc + col), a1 = __ldg(asrc + col + 1);
            float d0 = __ldg(adst + col), d1 = __ldg(adst + col + 1);
            sd[mt][0] += acc[mt][nt][0] * a0 + acc[mt][nt][1] * a1;
            dd[mt][0] += acc[mt][nt][0] * d0 + acc[mt][nt][1] * d1;
            sd[mt][1] += acc[mt][nt][2] * a0 + acc[mt][nt][3] * a1;
            dd[mt][1] += acc[mt][nt][2] * d0 + acc[mt][nt][3] * d1;
        }
    #pragma unroll
    for (int o = 1; o < 4; o <<= 1) {
        #pragma unroll
        for (int mt = 0; mt < 2; mt++)
            #pragma unroll
            for (int j = 0; j < 2; j++) {
                sd[mt][j] += __shfl_xor_sync(0xffffffffu, sd[mt][j], o);
                dd[mt][j] += __shfl_xor_sync(0xffffffffu, dd[mt][j], o);
            }
    }
    __syncthreads();
    float* red = (float*)smem;
    if (wn == 1 && tig == 0) {
        #pragma unroll
        for (int mt = 0; mt < 2; mt++)
            #pragma unroll
            for (int j = 0; j < 2; j++) {
                int lrow = m0 + mt * 16 + g + j * 8;
                red[lrow] = sd[mt][j];
                red[128 + lrow] = dd[mt][j];
            }
    }
    __syncthreads();
    float hsmax = -3.4e38f;
    if (wn == 0 && tig == 0) {
        #pragma unroll
        for (int mt = 0; mt < 2; mt++)
            #pragma unroll
            for (int j = 0; j < 2; j++) {
                int lrow = m0 + mt * 16 + g + j * 8;
                int gr = rowBase + lrow;
                if (gr < M) {
                    float sv = sd[mt][j] + red[lrow];
                    hs[gr] = sv;
                    hd[gr] = dd[mt][j] + red[128 + lrow];
                    hsmax = fmaxf(hsmax, sv);
                }
            }
    }
    #pragma unroll
    for (int o = 16; o; o >>= 1)
        hsmax = fmaxf(hsmax, __shfl_xor_sync(0xffffffffu, hsmax, o));
    if (wn == 0 && lane == 0) atomicMax(gmax, fkey(hsmax));
}

// ---------------------------------------------------------------------------
__device__ __forceinline__ float leaky02(float a) {
    return a > 0.f ? a : 0.2f * a;
}

// warp-per-node single-pass GAT agg; lane-parallel exp dedup; packed edges.
template <int C, bool POOL>
__global__ void __launch_bounds__(256)
gat_agg_k(const __half* __restrict__ h, const float* __restrict__ hs,
          const float* __restrict__ hd, const int* __restrict__ offs,
          const uint32_t* __restrict__ csre,
          const float* __restrict__ bias,
          const float* __restrict__ cptr, const unsigned* __restrict__ gmax,
          __half* __restrict__ xout, float* __restrict__ gsum, int n) {
    constexpr int VL = C / 32;
    __shared__ float sums[64];
    int w = (blockIdx.x * blockDim.x + threadIdx.x) >> 5;
    int lane = threadIdx.x & 31;
    bool active = (w < n);

    if (POOL) {
        if (threadIdx.x < 64) sums[threadIdx.x] = 0.f;
        __syncthreads();
    }

    float out[VL];
    if (active) {
        float c = *cptr;
        float hdn = hd[w];
        float ub = leaky02(funkey(*gmax) + hdn + fmaxf(c, 0.f));
        int beg = offs[w], end = offs[w + 1];

        float acc[VL];
        #pragma unroll
        for (int j = 0; j < VL; j++) acc[j] = 0.f;
        float denom = 0.f;
        float colpart = 0.f;          // lane-partial: each edge counted once
        const size_t loff = (size_t)lane * VL;

        int e = beg;
        for (; e + 8 <= end; e += 8) {
            uint32_t pk[8]; int s[8];
            #pragma unroll
            for (int q = 0; q < 8; q++) pk[q] = csre[e + q];
            #pragma unroll
            for (int q = 0; q < 8; q++) s[q] = (int)(pk[q] & 0xFFFFu);
            // lanes 0-7 compute exp for one edge each
            float myex = 0.f;
            {
                int q8 = lane & 7;
                float py = pkcol(pk[q8]);
                if (lane < 8) {
                    colpart += py;
                    myex = __expf(leaky02(hs[s[q8]] + hdn + py * c) - ub);
                }
            }
            float ex[8];
            #pragma unroll
            for (int q = 0; q < 8; q++) ex[q] = __shfl_sync(0xffffffffu, myex, q);
            #pragma unroll
            for (int q = 0; q < 8; q++) denom += ex[q];
            if (VL == 4) {
                uint2 r[8];
                #pragma unroll
                for (int q = 0; q < 8; q++)
                    r[q] = *(const uint2*)(h + (size_t)s[q] * C + loff);
                #pragma unroll
                for (int q = 0; q < 8; q++) {
                    float2 a = __half22float2(*(__half2*)&r[q].x);
                    float2 b = __half22float2(*(__half2*)&r[q].y);
                    acc[0] += ex[q] * a.x; acc[1] += ex[q] * a.y;
                    acc[2] += ex[q] * b.x; acc[3] += ex[q] * b.y;
                }
            } else {
                uint32_t r[8];
                #pragma unroll
                for (int q = 0; q < 8; q++)
                    r[q] = *(const uint32_t*)(h + (size_t)s[q] * C + loff);
                #pragma unroll
                for (int q = 0; q < 8; q++) {
                    float2 a = __half22float2(*(__half2*)&r[q]);
                    acc[0] += ex[q] * a.x; acc[1] += ex[q] * a.y;
                }
            }
        }
        // x4 mid tier (lanes 0-3 compute exp)
        for (; e + 4 <= end; e += 4) {
            uint32_t pk[4]; int s[4];
            #pragma unroll
            for (int q = 0; q < 4; q++) pk[q] = csre[e + q];
            #pragma unroll
            for (int q = 0; q < 4; q++) s[q] = (int)(pk[q] & 0xFFFFu);
            float myex = 0.f;
            {
                int q4 = lane & 3;
                float py = pkcol(pk[q4]);
                if (lane < 4) {
                    colpart += py;
                    myex = __expf(leaky02(hs[s[q4]] + hdn + py * c) - ub);
                }
            }
            float ex[4];
            #pragma unroll
            for (int q = 0; q < 4; q++) ex[q] = __shfl_sync(0xffffffffu, myex, q);
            #pragma unroll
            for (int q = 0; q < 4; q++) denom += ex[q];
            if (VL == 4) {
                uint2 r[4];
                #pragma unroll
                for (int q = 0; q < 4; q++)
                    r[q] = *(const uint2*)(h + (size_t)s[q] * C + loff);
                #pragma unroll
                for (int q = 0; q < 4; q++) {
                    float2 a = __half22float2(*(__half2*)&r[q].x);
                    float2 b = __half22float2(*(__half2*)&r[q].y);
                    acc[0] += ex[q] * a.x; acc[1] += ex[q] * a.y;
                    acc[2] += ex[q] * b.x; acc[3] += ex[q] * b.y;
                }
            } else {
                uint32_t r[4];
                #pragma unroll
                for (int q = 0; q < 4; q++)
                    r[q] = *(const uint32_t*)(h + (size_t)s[q] * C + loff);
                #pragma unroll
                for (int q = 0; q < 4; q++) {
                    float2 a = __half22float2(*(__half2*)&r[q]);
                    acc[0] += ex[q] * a.x; acc[1] += ex[q] * a.y;
                }
            }
        }
        // scalar remainder
        for (; e < end; e++) {
            uint32_t pk = csre[e];
            int s = (int)(pk & 0xFFFFu);
            float py = pkcol(pk);
            if (lane == 0) colpart += py;
            float ex = __expf(leaky02(hs[s] + hdn + py * c) - ub);
            denom += ex;
            if (VL == 4) {
                uint2 r = *(const uint2*)(h + (size_t)s * C + loff);
                float2 a = __half22float2(*(__half2*)&r.x);
                float2 b = __half22float2(*(__half2*)&r.y);
                acc[0] += ex * a.x; acc[1] += ex * a.y;
                acc[2] += ex * b.x; acc[3] += ex * b.y;
            } else {
                uint32_t r = *(const uint32_t*)(h + (size_t)s * C + loff);
                float2 a = __half22float2(*(__half2*)&r);
                acc[0] += ex * a.x; acc[1] += ex * a.y;
            }
        }
        // total colsum (each edge contributed exactly once across lanes)
        float colsum = colpart;
        #pragma unroll
        for (int o = 16; o; o >>= 1)
            colsum += __shfl_xor_sync(0xffffffffu, colsum, o);
        {   // self loop
            int deg = end - beg;
            float lattr = colsum / (float)(deg > 1 ? deg : 1);
            float aself = leaky02(hs[w] + hdn + lattr * c);
            float ex = __expf(aself - ub);
            denom += ex;
            if (VL == 4) {
                uint2 r = *(const uint2*)(h + (size_t)w * C + loff);
                float2 a = __half22float2(*(__half2*)&r.x);
                float2 b = __half22float2(*(__half2*)&r.y);
                acc[0] += ex * a.x; acc[1] += ex * a.y;
                acc[2] += ex * b.x; acc[3] += ex * b.y;
            } else {
                uint32_t r = *(const uint32_t*)(h + (size_t)w * C + loff);
                float2 a = __half22float2(*(__half2*)&r);
                acc[0] += ex * a.x; acc[1] += ex * a.y;
            }
        }
        float inv = 1.f / denom;
        #pragma unroll
        for (int j = 0; j < VL; j++) {
            float v = acc[j] * inv + bias[loff + j];
            out[j] = v > 0.f ? v : expm1f(v);
        }
        if (!POOL) {
            __half* xr = xout + (size_t)w * C + loff;
            if (VL == 4) {
                __half2 q0 = __floats2half2_rn(out[0], out[1]);
                __half2 q1 = __floats2half2_rn(out[2], out[3]);
                *(uint2*)xr = make_uint2(*(uint32_t*)&q0, *(uint32_t*)&q1);
            } else {
                __half2 q0 = __floats2half2_rn(out[0], out[1]);
                *(uint32_t*)xr = *(uint32_t*)&q0;
            }
        }
    }
    if (POOL) {
        if (active) {
            #pragma unroll
            for (int j = 0; j < VL; j++)
                atomicAdd(&sums[lane * VL + j], out[j]);
        }
        __syncthreads();
        if (threadIdx.x < 64) atomicAdd(&gsum[threadIdx.x], sums[threadIdx.x]);
    }
}

__global__ void head_k(const float* __restrict__ g, const float* __restrict__ xn1,
                       const float* __restrict__ xn2, const float* __restrict__ Wlin,
                       const float* __restrict__ blin, const float* __restrict__ Wc1,
                       const float* __restrict__ bc1, const float* __restrict__ Wc2,
                       const float* __restrict__ bc2, float* __restrict__ out, int n) {
    __shared__ float v[128];
    __shared__ float hh[16];
    int t = threadIdx.x;
    int gi = t >> 6, c = t & 63;
    const float* gg = g + gi * 64;
    const float* xn = gi ? xn2 : xn1;
    float inv = 1.f / (float)n;
    float s = blin[c];
    for (int k = 0; k < 64; k++) s += (gg[k] * inv) * Wlin[k * 64 + c];
    for (int k = 0; k < 16; k++) s += xn[k] * Wlin[(64 + k) * 64 + c];
    v[t] = s;
    __syncthreads();
    if (t < 16) {
        float a = bc1[t];
        for (int k = 0; k < 128; k++) a += v[k] * Wc1[k * 16 + t];
        hh[t] = fmaxf(a, 0.f);
    }
    __syncthreads();
    if (t < 3) {
        float a = bc2[t];
        for (int k = 0; k < 16; k++) a += hh[k] * Wc2[k * 3 + t];
        out[t] = a;
    }
}

// ---------------------------------------------------------------------------
extern "C" void kernel_launch(void* const* d_in, const int* in_sizes, int n_in,
                              void* d_out, int out_size) {
    const int IN = 7;
    const int N = in_sizes[0] / IN;
    const int E = in_sizes[2] / 2;

    static cudaStream_t s1 = nullptr, sCsr = nullptr;
    static cudaEvent_t evF = nullptr, evP = nullptr, evC = nullptr, evJ = nullptr;
    if (!s1) {
        cudaStreamCreateWithFlags(&s1, cudaStreamNonBlocking);
        cudaStreamCreateWithFlags(&sCsr, cudaStreamNonBlocking);
        cudaEventCreateWithFlags(&evF, cudaEventDisableTiming);
        cudaEventCreateWithFlags(&evP, cudaEventDisableTiming);
        cudaEventCreateWithFlags(&evC, cudaEventDisableTiming);
        cudaEventCreateWithFlags(&evJ, cudaEventDisableTiming);
        cudaFuncSetAttribute(gemm_mma_k<128>,
                             cudaFuncAttributeMaxDynamicSharedMemorySize, 53248);
        cudaFuncSetAttribute(gemm_mma_k<64>,
                             cudaFuncAttributeMaxDynamicSharedMemorySize, 36864);
    }

    float *b_hs, *b_hd, *p_g, *b_c;
    uint32_t* b_csre;
    __half *b_hh, *b_xh, *b_wfh, *b_wfl;
    unsigned* b_max;
    int *b_deg, *b_offs, *b_cursor, *b_tsum;
    cudaGetSymbolAddress((void**)&b_hh, g_hh);
    cudaGetSymbolAddress((void**)&b_xh, g_xh);
    cudaGetSymbolAddress((void**)&b_hs, g_hs);
    cudaGetSymbolAddress((void**)&b_hd, g_hd);
    cudaGetSymbolAddress((void**)&b_csre, g_csre);
    cudaGetSymbolAddress((void**)&p_g, g_gvec);
    cudaGetSymbolAddress((void**)&b_c, g_c);
    cudaGetSymbolAddress((void**)&b_max, g_maxhs);
    cudaGetSymbolAddress((void**)&b_deg, g_deg);
    cudaGetSymbolAddress((void**)&b_offs, g_offs);
    cudaGetSymbolAddress((void**)&b_cursor, g_cursor);
    cudaGetSymbolAddress((void**)&b_tsum, g_tsum);
    cudaGetSymbolAddress((void**)&b_wfh, g_wfh);
    cudaGetSymbolAddress((void**)&b_wfl, g_wfl);

    const float* x_in[2]  = {(const float*)d_in[0], (const float*)d_in[1]};
    const int*   ei[2]    = {(const int*)d_in[2], (const int*)d_in[3]};
    const float* xnorm[2] = {(const float*)d_in[4], (const float*)d_in[5]};
    const float* ecol[2]  = {(const float*)d_in[6], (const float*)d_in[7]};

    const float* W[3]; const float* asrc[3]; const float* adst[3];
    const float* We[3]; const float* ae[3]; const float* bb[3];
    for (int l = 0; l < 3; l++) {
        W[l]    = (const float*)d_in[8 + 6 * l + 0];
        asrc[l] = (const float*)d_in[8 + 6 * l + 1];
        adst[l] = (const float*)d_in[8 + 6 * l + 2];
        We[l]   = (const float*)d_in[8 + 6 * l + 3];
        ae[l]   = (const float*)d_in[8 + 6 * l + 4];
        bb[l]   = (const float*)d_in[8 + 6 * l + 5];
    }
    const float* Wlin = (const float*)d_in[26];
    const float* blin = (const float*)d_in[27];
    const float* Wc1  = (const float*)d_in[28];
    const float* bc1  = (const float*)d_in[29];
    const float* Wc2  = (const float*)d_in[30];
    const float* bc2  = (const float*)d_in[31];

    const int eHalfBlocks = (E + 255) / 256;
    const int nT = (N + TILE - 1) / TILE;
    const int tcBlocks = (N + 127) / 128;
    const int g7Blocks = (N + 7) / 8;
    const int aggBlocks = (N * 32 + 255) / 256;

    // fork point
    cudaEventRecord(evF, 0);
    cudaStreamWaitEvent(sCsr, evF, 0);
    cudaStreamWaitEvent(s1, evF, 0);

    // batched CSR build on side stream
    cudaMemsetAsync(b_deg, 0, 2 * MAX_N * sizeof(int), sCsr);
    build_deg_k<<<eHalfBlocks, 256, 0, sCsr>>>(ei[0], ei[1], b_deg, E);
    scan1_k<<<2 * nT, 256, 0, sCsr>>>(b_deg, b_tsum, N, nT);
    scan2_k<<<1, 256, 0, sCsr>>>(b_tsum, nT);
    scan3_k<<<2 * nT, TILE, 0, sCsr>>>(b_deg, b_tsum, b_offs, b_cursor, N, nT);
    scatter_k<<<eHalfBlocks, 256, 0, sCsr>>>(ei[0], ecol[0], ei[1], ecol[1],
                                             b_cursor, b_csre, E);
    cudaEventRecord(evC, sCsr);

    // prologue on stream 0 (graph-invariant)
    cudaMemsetAsync(p_g, 0, 128 * sizeof(float), 0);
    cudaMemsetAsync(b_max, 0, 6 * sizeof(unsigned), 0);
    wsplit_k<<<(128 * 128 + 255) / 256, 256, 0, 0>>>(W[1], b_wfh, b_wfl, 128 * 128);
    wsplit_k<<<(128 * 64 + 255) / 256, 256, 0, 0>>>(W[2], b_wfh + 128 * 128,
                                                    b_wfl + 128 * 128, 128 * 64);
    cscalar3_k<<<1, 96, 0, 0>>>(We[0], ae[0], We[1], ae[1], We[2], ae[2], b_c);
    cudaEventRecord(evP, 0);
    cudaStreamWaitEvent(s1, evP, 0);

    // per-graph chains on two streams
    for (int gph = 0; gph < 2; gph++) {
        cudaStream_t st = gph ? s1 : (cudaStream_t)0;
        __half* p_hh = b_hh + (size_t)gph * MAX_N * 128;
        __half* p_xh = b_xh + (size_t)gph * MAX_N * 128;
        float* p_hs = b_hs + gph * MAX_N;
        float* p_hd = b_hd + gph * MAX_N;
        uint32_t* p_csre = b_csre + (size_t)gph * MAX_E;
        int* p_offs = b_offs + gph * (MAX_N + 1);

        gemm7_k<<<g7Blocks, 256, 0, st>>>(x_in[gph], W[0], asrc[0], adst[0],
                                          p_hh, p_hs, p_hd, b_max + 0 + gph, N);
        cudaStreamWaitEvent(st, evC, 0);

        gat_agg_k<128, false><<<aggBlocks, 256, 0, st>>>(
            p_hh, p_hs, p_hd, p_offs, p_csre, bb[0], b_c + 0,
            b_max + 0 + gph, p_xh, nullptr, N);
        gemm_mma_k<128><<<tcBlocks, 256, 53248, st>>>(
            p_xh, b_wfh, b_wfl, asrc[1], adst[1], p_hh, p_hs, p_hd,
            b_max + 2 + gph, N);
        gat_agg_k<128, false><<<aggBlocks, 256, 0, st>>>(
            p_hh, p_hs, p_hd, p_offs, p_csre, bb[1], b_c + 1,
            b_max + 2 + gph, p_xh, nullptr, N);
        gemm_mma_k<64><<<tcBlocks, 256, 36864, st>>>(
            p_xh, b_wfh + 128 * 128, b_wfl + 128 * 128, asrc[2], adst[2],
            p_hh, p_hs, p_hd, b_max + 4 + gph, N);
        gat_agg_k<64, true><<<aggBlocks, 256, 0, st>>>(
            p_hh, p_hs, p_hd, p_offs, p_csre, bb[2], b_c + 2,
            b_max + 4 + gph, nullptr, p_g + gph * 64, N);
    }

    cudaEventRecord(evJ, s1);
    cudaStreamWaitEvent((cudaStream_t)0, evJ, 0);
    head_k<<<1, 128, 0, 0>>>(p_g, xnorm[0], xnorm[1], Wlin, blin, Wc1, bc1, Wc2, bc2,
                             (float*)d_out, N);
}

// round 17
// speedup vs baseline: 1.0954x; 1.0954x over previous
#include <cuda_runtime.h>
#include <cuda_bf16.h>
#include <cuda_fp16.h>
#include <math.h>
#include <stdint.h>

// ---------------------------------------------------------------------------
// SpatialModel: 3-layer GATConv on two graphs (N=50000, E=800000), mean pool,
// MLP head -> [1,3] logits.
//
// R17: R15 agg loop shape (warp-redundant scalars, proven fast) + 4B packed
// edge records (src:16 | col:fp16) -- half the edge-stream bytes. fp16 MMA
// GEMM (A exact, W hi+lo), fp16 h/x payloads, fused mean-pool layer 2,
// two-stream pipeline, batched CSR side stream.
// ---------------------------------------------------------------------------

#define MAX_N 50000
#define MAX_E 800000
#define TILE 512

__device__ __align__(16) __half g_hh[2][MAX_N * 128];
__device__ __align__(16) __half g_xh[2][MAX_N * 128];
__device__ float g_hs[2][MAX_N];
__device__ float g_hd[2][MAX_N];
__device__ int   g_deg[2][MAX_N];
__device__ int   g_offs[2][MAX_N + 1];
__device__ int   g_cursor[2][MAX_N];
__device__ __align__(16) uint32_t g_csre[2][MAX_E];   // src:16 | col(fp16):16
__device__ int   g_tsum[2][128];
__device__ float g_c[3];
__device__ unsigned g_maxhs[6];
__device__ float g_gvec[128];
__device__ __align__(16) __half g_wfh[2][128 * 128];
__device__ __align__(16) __half g_wfl[2][128 * 128];

// ---------------------------------------------------------------------------
__device__ __forceinline__ uint32_t smem_u32(const void* p) {
    uint32_t a;
    asm("{ .reg .u64 t; cvta.to.shared.u64 t, %1; cvt.u32.u64 %0, t; }"
        : "=r"(a) : "l"(p));
    return a;
}
__device__ __forceinline__ unsigned fkey(float f) {
    int i = __float_as_int(f);
    return i >= 0 ? ((unsigned)i | 0x80000000u) : ~(unsigned)i;
}
__device__ __forceinline__ float funkey(unsigned k) {
    return (k & 0x80000000u) ? __int_as_float((int)(k & 0x7FFFFFFFu))
                             : __int_as_float((int)~k);
}
__device__ __forceinline__ float pkcol(uint32_t pk) {
    return __half2float(__ushort_as_half((unsigned short)(pk >> 16)));
}
#define LDSM_X4(r0, r1, r2, r3, addr)                                          \
    asm volatile("ldmatrix.sync.aligned.m8n8.x4.shared.b16 {%0,%1,%2,%3}, [%4];" \
                 : "=r"(r0), "=r"(r1), "=r"(r2), "=r"(r3) : "r"(addr))
#define LDSM_X4_T(r0, r1, r2, r3, addr)                                        \
    asm volatile("ldmatrix.sync.aligned.m8n8.x4.trans.shared.b16 {%0,%1,%2,%3}, [%4];" \
                 : "=r"(r0), "=r"(r1), "=r"(r2), "=r"(r3) : "r"(addr))
__device__ __forceinline__ void mma_f16(float* c, uint32_t a0, uint32_t a1,
                                        uint32_t a2, uint32_t a3,
                                        uint32_t b0, uint32_t b1) {
    asm volatile(
        "mma.sync.aligned.m16n8k16.row.col.f32.f16.f16.f32 "
        "{%0,%1,%2,%3}, {%4,%5,%6,%7}, {%8,%9}, {%0,%1,%2,%3};"
        : "+f"(c[0]), "+f"(c[1]), "+f"(c[2]), "+f"(c[3])
        : "r"(a0), "r"(a1), "r"(a2), "r"(a3), "r"(b0), "r"(b1));
}

// ---------------------------------------------------------------------------
__global__ void build_deg_k(const int* __restrict__ ei0, const int* __restrict__ ei1,
                            int* deg, int E) {
    int i = (blockIdx.x * blockDim.x + threadIdx.x) * 2;
    if (i >= 2 * E) return;
    int g = (i >= E);
    int j = i - g * E;
    const int* dst = (g ? ei1 : ei0) + E;
    int d0 = dst[j];
    int d1 = dst[j + 1];
    atomicAdd(&deg[g * MAX_N + d0], 1);
    atomicAdd(&deg[g * MAX_N + d1], 1);
}

__global__ void scan1_k(const int* __restrict__ deg, int* tsum, int n, int nT) {
    __shared__ int sh[256];
    int bx = blockIdx.x, t = threadIdx.x;
    int g = (bx >= nT);
    int b = bx - g * nT;
    const int* dg = deg + g * MAX_N;
    int i0 = b * TILE;
    int s = 0;
    int i = i0 + t;        if (i < n) s += dg[i];
    i = i0 + 256 + t;      if (i < n) s += dg[i];
    sh[t] = s;
    __syncthreads();
    for (int o = 128; o; o >>= 1) { if (t < o) sh[t] += sh[t + o]; __syncthreads(); }
    if (t == 0) tsum[g * 128 + b] = sh[0];
}
__global__ void scan2_k(int* tsum, int nT) {
    __shared__ int sh[256];
    int t = threadIdx.x;
    int g = t >> 7, tl = t & 127;
    int v0 = (tl < nT) ? tsum[g * 128 + tl] : 0;
    sh[t] = v0;
    __syncthreads();
    for (int d = 1; d < 128; d <<= 1) {
        int v = (tl >= d) ? sh[t - d] : 0;
        __syncthreads();
        sh[t] += v;
        __syncthreads();
    }
    if (tl < nT) tsum[g * 128 + tl] = sh[t] - v0;
}
__global__ void scan3_k(const int* __restrict__ deg, const int* __restrict__ tsum,
                        int* offs, int* cursor, int n, int nT) {
    __shared__ int sh[TILE];
    int bx = blockIdx.x, t = threadIdx.x;
    int g = (bx >= nT);
    int b = bx - g * nT;
    const int* dg = deg + g * MAX_N;
    const int* ts = tsum + g * 128;
    int* of = offs + g * (MAX_N + 1);
    int* cu = cursor + g * MAX_N;
    int i = b * TILE + t;
    int d = (i < n) ? dg[i] : 0;
    sh[t] = d;
    __syncthreads();
    for (int o = 1; o < TILE; o <<= 1) {
        int v = (t >= o) ? sh[t - o] : 0;
        __syncthreads();
        sh[t] += v;
        __syncthreads();
    }
    if (i < n) {
        int base = ts[b];
        int off = base + sh[t] - d;
        of[i] = off;
        cu[i] = off;
        if (i == n - 1) of[n] = base + sh[t];
    }
}

__global__ void scatter_k(const int* __restrict__ ei0, const float* __restrict__ col0,
                          const int* __restrict__ ei1, const float* __restrict__ col1,
                          int* cursor, uint32_t* csre, int E) {
    int i = (blockIdx.x * blockDim.x + threadIdx.x) * 2;
    if (i >= 2 * E) return;
    int g = (i >= E);
    int j = i - g * E;
    const int* ei = g ? ei1 : ei0;
    const float* col = g ? col1 : col0;
    int* cur = cursor + g * MAX_N;
    uint32_t* cs = csre + (size_t)g * MAX_E;
    int s0 = ei[j], s1 = ei[j + 1];
    int d0 = ei[E + j], d1 = ei[E + j + 1];
    uint32_t k0 = (uint32_t)s0 |
                  ((uint32_t)__half_as_ushort(__float2half_rn(col[j])) << 16);
    uint32_t k1 = (uint32_t)s1 |
                  ((uint32_t)__half_as_ushort(__float2half_rn(col[j + 1])) << 16);
    int p0 = atomicAdd(&cur[d0], 1);
    int p1 = atomicAdd(&cur[d1], 1);
    cs[p0] = k0;
    cs[p1] = k1;
}

// ---------------------------------------------------------------------------
__global__ void wsplit_k(const float* __restrict__ W, __half* hi, __half* lo, int n) {
    int i = blockIdx.x * blockDim.x + threadIdx.x;
    if (i >= n) return;
    float v = W[i];
    __half h = __float2half_rn(v);
    hi[i] = h;
    lo[i] = __float2half_rn(v - __half2float(h));
}

__global__ void cscalar3_k(const float* __restrict__ We1, const float* __restrict__ ae1,
                           const float* __restrict__ We2, const float* __restrict__ ae2,
                           const float* __restrict__ We3, const float* __restrict__ ae3,
                           float* out) {
    int w = threadIdx.x >> 5, lane = threadIdx.x & 31;
    if (w >= 3) return;
    const float* We = (w == 0) ? We1 : (w == 1) ? We2 : We3;
    const float* ae = (w == 0) ? ae1 : (w == 1) ? ae2 : ae3;
    int C = (w == 2) ? 64 : 128;
    float s = 0.f;
    for (int k = lane; k < C; k += 32) s += We[k] * ae[k];
    #pragma unroll
    for (int o = 16; o; o >>= 1) s += __shfl_xor_sync(0xffffffffu, s, o);
    if (lane == 0) out[w] = s;
}

// ---------------------------------------------------------------------------
__global__ void __launch_bounds__(256)
gemm7_k(const float* __restrict__ x, const float* __restrict__ W,
        const float* __restrict__ asrc, const float* __restrict__ adst,
        __half* __restrict__ h, float* __restrict__ hs, float* __restrict__ hd,
        unsigned* __restrict__ gmax, int M) {
    __shared__ float Ws[7 * 128], As[128], Ad[128];
    __shared__ float wmax[8];
    int t = threadIdx.x;
    for (int i = t; i < 7 * 128; i += 256) Ws[i] = W[i];
    if (t < 128) { As[t] = asrc[t]; Ad[t] = adst[t]; }
    __syncthreads();
    int r = blockIdx.x * 8 + (t >> 5);
    bool active = (r < M);
    int lane = t & 31, c0 = lane * 4;
    float s = 0.f, d = 0.f;
    if (active) {
        float xv[7];
        #pragma unroll
        for (int k = 0; k < 7; k++) xv[k] = x[(size_t)r * 7 + k];
        float out[4];
        #pragma unroll
        for (int j = 0; j < 4; j++) {
            float acc = 0.f;
            #pragma unroll
            for (int k = 0; k < 7; k++) acc += xv[k] * Ws[k * 128 + c0 + j];
            out[j] = acc;
        }
        __half2 p0 = __floats2half2_rn(out[0], out[1]);
        __half2 p1 = __floats2half2_rn(out[2], out[3]);
        uint2 u = make_uint2(*(uint32_t*)&p0, *(uint32_t*)&p1);
        *(uint2*)(h + (size_t)r * 128 + c0) = u;
        s = out[0] * As[c0] + out[1] * As[c0 + 1] + out[2] * As[c0 + 2] + out[3] * As[c0 + 3];
        d = out[0] * Ad[c0] + out[1] * Ad[c0 + 1] + out[2] * Ad[c0 + 2] + out[3] * Ad[c0 + 3];
        #pragma unroll
        for (int o = 16; o; o >>= 1) {
            s += __shfl_xor_sync(0xffffffffu, s, o);
            d += __shfl_xor_sync(0xffffffffu, d, o);
        }
        if (lane == 0) { hs[r] = s; hd[r] = d; }
    }
    if (lane == 0) wmax[t >> 5] = active ? s : -3.4e38f;
    __syncthreads();
    if (t == 0) {
        float m = wmax[0];
        #pragma unroll
        for (int i = 1; i < 8; i++) m = fmaxf(m, wmax[i]);
        atomicMax(gmax, fkey(m));
    }
}

// ---------------------------------------------------------------------------
template <int CN>
__global__ void __launch_bounds__(256, 2)
gemm_mma_k(const __half* __restrict__ A, const __half* __restrict__ Bh,
           const __half* __restrict__ Bl,
           const float* __restrict__ asrc, const float* __restrict__ adst,
           __half* __restrict__ H, float* __restrict__ hs, float* __restrict__ hd,
           unsigned* __restrict__ gmax, int M) {
    extern __shared__ char smem[];
    constexpr int SA = 72;
    constexpr int SB = CN + 8;
    constexpr int AS = 0;
    constexpr int BH = 128 * SA * 2;
    constexpr int BL = BH + 64 * SB * 2;
    constexpr int NT = CN / 16;
    constexpr int NC8 = CN / 8;

    int tid = threadIdx.x, lane = tid & 31, warp = tid >> 5;
    const int rowBase = blockIdx.x * 128;

    __half* as = (__half*)(smem + AS);
    __half* bs_h = (__half*)(smem + BH);
    __half* bs_l = (__half*)(smem + BL);

    int wm = warp >> 1, wn = warp & 1;
    int m0 = wm * 32, n0 = wn * (CN / 2);

    float acc[2][NT][4];
    #pragma unroll
    for (int a = 0; a < 2; a++)
        #pragma unroll
        for (int b = 0; b < NT; b++)
            #pragma unroll
            for (int q = 0; q < 4; q++) acc[a][b][q] = 0.f;

    int lr = lane & 15, lc = lane >> 4;
    uint32_t sb_a = smem_u32(as);
    uint32_t sb_bh = smem_u32(bs_h), sb_bl = smem_u32(bs_l);

    #pragma unroll
    for (int kc = 0; kc < 128; kc += 64) {
        #pragma unroll
        for (int q = 0; q < 4; q++) {
            int i = q * 256 + tid;
            int r = i >> 3, c8 = i & 7;
            int gr = rowBase + r;
            uint4 u = make_uint4(0u, 0u, 0u, 0u);
            if (gr < M) u = *(const uint4*)(A + (size_t)gr * 128 + kc + c8 * 8);
            *(uint4*)(as + r * SA + c8 * 8) = u;
        }
        for (int i = tid; i < 64 * NC8; i += 256) {
            int r = i / NC8, c8 = i % NC8;
            int gi = (kc + r) * NC8 + c8;
            *(uint4*)(bs_h + r * SB + c8 * 8) = ((const uint4*)Bh)[gi];
            *(uint4*)(bs_l + r * SB + c8 * 8) = ((const uint4*)Bl)[gi];
        }
        __syncthreads();

        #pragma unroll
        for (int ks = 0; ks < 4; ks++) {
            int k0 = ks * 16;
            uint32_t af[2][4];
            #pragma unroll
            for (int mt = 0; mt < 2; mt++) {
                uint32_t off = ((m0 + mt * 16 + lr) * SA + k0 + lc * 8) * 2;
                LDSM_X4(af[mt][0], af[mt][1], af[mt][2], af[mt][3], sb_a + off);
            }
            #pragma unroll
            for (int n16 = 0; n16 < NT / 2; n16++) {
                uint32_t off = ((k0 + lr) * SB + n0 + n16 * 16 + lc * 8) * 2;
                uint32_t b0h, b1h, b2h, b3h, b0l, b1l, b2l, b3l;
                LDSM_X4_T(b0h, b1h, b2h, b3h, sb_bh + off);
                LDSM_X4_T(b0l, b1l, b2l, b3l, sb_bl + off);
                int nt0 = 2 * n16, nt1 = 2 * n16 + 1;
                #pragma unroll
                for (int mt = 0; mt < 2; mt++) {
                    mma_f16(acc[mt][nt0], af[mt][0], af[mt][1], af[mt][2], af[mt][3], b0h, b1h);
                    mma_f16(acc[mt][nt0], af[mt][0], af[mt][1], af[mt][2], af[mt][3], b0l, b1l);
                    mma_f16(acc[mt][nt1], af[mt][0], af[mt][1], af[mt][2], af[mt][3], b2h, b3h);
                    mma_f16(acc[mt][nt1], af[mt][0], af[mt][1], af[mt][2], af[mt][3], b2l, b3l);
                }
            }
        }
        __syncthreads();
    }

    int g = lane >> 2, tig = lane & 3;
    #pragma unroll
    for (int mt = 0; mt < 2; mt++) {
        int r0 = rowBase + m0 + mt * 16 + g;
        int r1 = r0 + 8;
        #pragma unroll
        for (int nt = 0; nt < NT; nt++) {
            int col = n0 + nt * 8 + tig * 2;
            if (r0 < M)
                *(__half2*)(H + (size_t)r0 * CN + col) =
                    __floats2half2_rn(acc[mt][nt][0], acc[mt][nt][1]);
            if (r1 < M)
                *(__half2*)(H + (size_t)r1 * CN + col) =
                    __floats2half2_rn(acc[mt][nt][2], acc[mt][nt][3]);
        }
    }

    float sd[2][2] = {}, dd[2][2] = {};
    #pragma unroll
    for (int mt = 0; mt < 2; mt++)
        #pragma unroll
        for (int nt = 0; nt < NT; nt++) {
            int col = n0 + nt * 8 + tig * 2;
            float a0 = __ldg(asrc + col), a1 = __ldg(asrc + col + 1);
            float d0 = __ldg(adst + col), d1 = __ldg(adst + col + 1);
            sd[mt][0] += acc[mt][nt][0] * a0 + acc[mt][nt][1] * a1;
            dd[mt][0] += acc[mt][nt][0] * d0 + acc[mt][nt][1] * d1;
            sd[mt][1] += acc[mt][nt][2] * a0 + acc[mt][nt][3] * a1;
            dd[mt][1] += acc[mt][nt][2] * d0 + acc[mt][nt][3] * d1;
        }
    #pragma unroll
    for (int o = 1; o < 4; o <<= 1) {
        #pragma unroll
        for (int mt = 0; mt < 2; mt++)
            #pragma unroll
            for (int j = 0; j < 2; j++) {
                sd[mt][j] += __shfl_xor_sync(0xffffffffu, sd[mt][j], o);
                dd[mt][j] += __shfl_xor_sync(0xffffffffu, dd[mt][j], o);
            }
    }
    __syncthreads();
    float* red = (float*)smem;
    if (wn == 1 && tig == 0) {
        #pragma unroll
        for (int mt = 0; mt < 2; mt++)
            #pragma unroll
            for (int j = 0; j < 2; j++) {
                int lrow = m0 + mt * 16 + g + j * 8;
                red[lrow] = sd[mt][j];
                red[128 + lrow] = dd[mt][j];
            }
    }
    __syncthreads();
    float hsmax = -3.4e38f;
    if (wn == 0 && tig == 0) {
        #pragma unroll
        for (int mt = 0; mt < 2; mt++)
            #pragma unroll
            for (int j = 0; j < 2; j++) {
                int lrow = m0 + mt * 16 + g + j * 8;
                int gr = rowBase + lrow;
                if (gr < M) {
                    float sv = sd[mt][j] + red[lrow];
                    hs[gr] = sv;
                    hd[gr] = dd[mt][j] + red[128 + lrow];
                    hsmax = fmaxf(hsmax, sv);
                }
            }
    }
    #pragma unroll
    for (int o = 16; o; o >>= 1)
        hsmax = fmaxf(hsmax, __shfl_xor_sync(0xffffffffu, hsmax, o));
    if (wn == 0 && lane == 0) atomicMax(gmax, fkey(hsmax));
}

// ---------------------------------------------------------------------------
__device__ __forceinline__ float leaky02(float a) {
    return a > 0.f ? a : 0.2f * a;
}

// warp-per-node single-pass GAT agg; R15 loop shape, packed 4B edges.
template <int C, bool POOL>
__global__ void __launch_bounds__(256)
gat_agg_k(const __half* __restrict__ h, const float* __restrict__ hs,
          const float* __restrict__ hd, const int* __restrict__ offs,
          const uint32_t* __restrict__ csre,
          const float* __restrict__ bias,
          const float* __restrict__ cptr, const unsigned* __restrict__ gmax,
          __half* __restrict__ xout, float* __restrict__ gsum, int n) {
    constexpr int VL = C / 32;
    __shared__ float sums[64];
    int w = (blockIdx.x * blockDim.x + threadIdx.x) >> 5;
    int lane = threadIdx.x & 31;
    bool active = (w < n);

    if (POOL) {
        if (threadIdx.x < 64) sums[threadIdx.x] = 0.f;
        __syncthreads();
    }

    float out[VL];
    if (active) {
        float c = *cptr;
        float hdn = hd[w];
        float ub = leaky02(funkey(*gmax) + hdn + fmaxf(c, 0.f));
        int beg = offs[w], end = offs[w + 1];

        float acc[VL];
        #pragma unroll
        for (int j = 0; j < VL; j++) acc[j] = 0.f;
        float denom = 0.f;
        float colsum = 0.f;
        const size_t loff = (size_t)lane * VL;

        int e = beg;
        for (; e + 8 <= end; e += 8) {
            uint32_t pk[8]; int s[8]; float py[8]; float ex[8];
            #pragma unroll
            for (int q = 0; q < 8; q++) pk[q] = csre[e + q];
            #pragma unroll
            for (int q = 0; q < 8; q++) {
                s[q] = (int)(pk[q] & 0xFFFFu);
                py[q] = pkcol(pk[q]);
                colsum += py[q];
            }
            #pragma unroll
            for (int q = 0; q < 8; q++) {
                ex[q] = __expf(leaky02(hs[s[q]] + hdn + py[q] * c) - ub);
                denom += ex[q];
            }
            if (VL == 4) {
                uint2 r[8];
                #pragma unroll
                for (int q = 0; q < 8; q++)
                    r[q] = *(const uint2*)(h + (size_t)s[q] * C + loff);
                #pragma unroll
                for (int q = 0; q < 8; q++) {
                    float2 a = __half22float2(*(__half2*)&r[q].x);
                    float2 b = __half22float2(*(__half2*)&r[q].y);
                    acc[0] += ex[q] * a.x; acc[1] += ex[q] * a.y;
                    acc[2] += ex[q] * b.x; acc[3] += ex[q] * b.y;
                }
            } else {
                uint32_t r[8];
                #pragma unroll
                for (int q = 0; q < 8; q++)
                    r[q] = *(const uint32_t*)(h + (size_t)s[q] * C + loff);
                #pragma unroll
                for (int q = 0; q < 8; q++) {
                    float2 a = __half22float2(*(__half2*)&r[q]);
                    acc[0] += ex[q] * a.x; acc[1] += ex[q] * a.y;
                }
            }
        }
        for (; e + 4 <= end; e += 4) {
            uint32_t pk[4]; int s[4]; float py[4]; float ex[4];
            #pragma unroll
            for (int q = 0; q < 4; q++) pk[q] = csre[e + q];
            #pragma unroll
            for (int q = 0; q < 4; q++) {
                s[q] = (int)(pk[q] & 0xFFFFu);
                py[q] = pkcol(pk[q]);
                colsum += py[q];
            }
            #pragma unroll
            for (int q = 0; q < 4; q++) {
                ex[q] = __expf(leaky02(hs[s[q]] + hdn + py[q] * c) - ub);
                denom += ex[q];
            }
            if (VL == 4) {
                uint2 r[4];
                #pragma unroll
                for (int q = 0; q < 4; q++)
                    r[q] = *(const uint2*)(h + (size_t)s[q] * C + loff);
                #pragma unroll
                for (int q = 0; q < 4; q++) {
                    float2 a = __half22float2(*(__half2*)&r[q].x);
                    float2 b = __half22float2(*(__half2*)&r[q].y);
                    acc[0] += ex[q] * a.x; acc[1] += ex[q] * a.y;
                    acc[2] += ex[q] * b.x; acc[3] += ex[q] * b.y;
                }
            } else {
                uint32_t r[4];
                #pragma unroll
                for (int q = 0; q < 4; q++)
                    r[q] = *(const uint32_t*)(h + (size_t)s[q] * C + loff);
                #pragma unroll
                for (int q = 0; q < 4; q++) {
                    float2 a = __half22float2(*(__half2*)&r[q]);
                    acc[0] += ex[q] * a.x; acc[1] += ex[q] * a.y;
                }
            }
        }
        for (; e < end; e++) {
            uint32_t pk = csre[e];
            int s = (int)(pk & 0xFFFFu);
            float py = pkcol(pk);
            colsum += py;
            float ex = __expf(leaky02(hs[s] + hdn + py * c) - ub);
            denom += ex;
            if (VL == 4) {
                uint2 r = *(const uint2*)(h + (size_t)s * C + loff);
                float2 a = __half22float2(*(__half2*)&r.x);
                float2 b = __half22float2(*(__half2*)&r.y);
                acc[0] += ex * a.x; acc[1] += ex * a.y;
                acc[2] += ex * b.x; acc[3] += ex * b.y;
            } else {
                uint32_t r = *(const uint32_t*)(h + (size_t)s * C + loff);
                float2 a = __half22float2(*(__half2*)&r);
                acc[0] += ex * a.x; acc[1] += ex * a.y;
            }
        }
        {   // self loop
            int deg = end - beg;
            float lattr = colsum / (float)(deg > 1 ? deg : 1);
            float aself = leaky02(hs[w] + hdn + lattr * c);
            float ex = __expf(aself - ub);
            denom += ex;
            if (VL == 4) {
                uint2 r = *(const uint2*)(h + (size_t)w * C + loff);
                float2 a = __half22float2(*(__half2*)&r.x);
                float2 b = __half22float2(*(__half2*)&r.y);
                acc[0] += ex * a.x; acc[1] += ex * a.y;
                acc[2] += ex * b.x; acc[3] += ex * b.y;
            } else {
                uint32_t r = *(const uint32_t*)(h + (size_t)w * C + loff);
                float2 a = __half22float2(*(__half2*)&r);
                acc[0] += ex * a.x; acc[1] += ex * a.y;
            }
        }
        float inv = 1.f / denom;
        #pragma unroll
        for (int j = 0; j < VL; j++) {
            float v = acc[j] * inv + bias[loff + j];
            out[j] = v > 0.f ? v : expm1f(v);
        }
        if (!POOL) {
            __half* xr = xout + (size_t)w * C + loff;
            if (VL == 4) {
                __half2 q0 = __floats2half2_rn(out[0], out[1]);
                __half2 q1 = __floats2half2_rn(out[2], out[3]);
                *(uint2*)xr = make_uint2(*(uint32_t*)&q0, *(uint32_t*)&q1);
            } else {
                __half2 q0 = __floats2half2_rn(out[0], out[1]);
                *(uint32_t*)xr = *(uint32_t*)&q0;
            }
        }
    }
    if (POOL) {
        if (active) {
            #pragma unroll
            for (int j = 0; j < VL; j++)
                atomicAdd(&sums[lane * VL + j], out[j]);
        }
        __syncthreads();
        if (threadIdx.x < 64) atomicAdd(&gsum[threadIdx.x], sums[threadIdx.x]);
    }
}

__global__ void head_k(const float* __restrict__ g, const float* __restrict__ xn1,
                       const float* __restrict__ xn2, const float* __restrict__ Wlin,
                       const float* __restrict__ blin, const float* __restrict__ Wc1,
                       const float* __restrict__ bc1, const float* __restrict__ Wc2,
                       const float* __restrict__ bc2, float* __restrict__ out, int n) {
    __shared__ float v[128];
    __shared__ float hh[16];
    int t = threadIdx.x;
    int gi = t >> 6, c = t & 63;
    const float* gg = g + gi * 64;
    const float* xn = gi ? xn2 : xn1;
    float inv = 1.f / (float)n;
    float s = blin[c];
    for (int k = 0; k < 64; k++) s += (gg[k] * inv) * Wlin[k * 64 + c];
    for (int k = 0; k < 16; k++) s += xn[k] * Wlin[(64 + k) * 64 + c];
    v[t] = s;
    __syncthreads();
    if (t < 16) {
        float a = bc1[t];
        for (int k = 0; k < 128; k++) a += v[k] * Wc1[k * 16 + t];
        hh[t] = fmaxf(a, 0.f);
    }
    __syncthreads();
    if (t < 3) {
        float a = bc2[t];
        for (int k = 0; k < 16; k++) a += hh[k] * Wc2[k * 3 + t];
        out[t] = a;
    }
}

// ---------------------------------------------------------------------------
extern "C" void kernel_launch(void* const* d_in, const int* in_sizes, int n_in,
                              void* d_out, int out_size) {
    const int IN = 7;
    const int N = in_sizes[0] / IN;
    const int E = in_sizes[2] / 2;

    static cudaStream_t s1 = nullptr, sCsr = nullptr;
    static cudaEvent_t evF = nullptr, evP = nullptr, evC = nullptr, evJ = nullptr;
    if (!s1) {
        cudaStreamCreateWithFlags(&s1, cudaStreamNonBlocking);
        cudaStreamCreateWithFlags(&sCsr, cudaStreamNonBlocking);
        cudaEventCreateWithFlags(&evF, cudaEventDisableTiming);
        cudaEventCreateWithFlags(&evP, cudaEventDisableTiming);
        cudaEventCreateWithFlags(&evC, cudaEventDisableTiming);
        cudaEventCreateWithFlags(&evJ, cudaEventDisableTiming);
        cudaFuncSetAttribute(gemm_mma_k<128>,
                             cudaFuncAttributeMaxDynamicSharedMemorySize, 53248);
        cudaFuncSetAttribute(gemm_mma_k<64>,
                             cudaFuncAttributeMaxDynamicSharedMemorySize, 36864);
    }

    float *b_hs, *b_hd, *p_g, *b_c;
    uint32_t* b_csre;
    __half *b_hh, *b_xh, *b_wfh, *b_wfl;
    unsigned* b_max;
    int *b_deg, *b_offs, *b_cursor, *b_tsum;
    cudaGetSymbolAddress((void**)&b_hh, g_hh);
    cudaGetSymbolAddress((void**)&b_xh, g_xh);
    cudaGetSymbolAddress((void**)&b_hs, g_hs);
    cudaGetSymbolAddress((void**)&b_hd, g_hd);
    cudaGetSymbolAddress((void**)&b_csre, g_csre);
    cudaGetSymbolAddress((void**)&p_g, g_gvec);
    cudaGetSymbolAddress((void**)&b_c, g_c);
    cudaGetSymbolAddress((void**)&b_max, g_maxhs);
    cudaGetSymbolAddress((void**)&b_deg, g_deg);
    cudaGetSymbolAddress((void**)&b_offs, g_offs);
    cudaGetSymbolAddress((void**)&b_cursor, g_cursor);
    cudaGetSymbolAddress((void**)&b_tsum, g_tsum);
    cudaGetSymbolAddress((void**)&b_wfh, g_wfh);
    cudaGetSymbolAddress((void**)&b_wfl, g_wfl);

    const float* x_in[2]  = {(const float*)d_in[0], (const float*)d_in[1]};
    const int*   ei[2]    = {(const int*)d_in[2], (const int*)d_in[3]};
    const float* xnorm[2] = {(const float*)d_in[4], (const float*)d_in[5]};
    const float* ecol[2]  = {(const float*)d_in[6], (const float*)d_in[7]};

    const float* W[3]; const float* asrc[3]; const float* adst[3];
    const float* We[3]; const float* ae[3]; const float* bb[3];
    for (int l = 0; l < 3; l++) {
        W[l]    = (const float*)d_in[8 + 6 * l + 0];
        asrc[l] = (const float*)d_in[8 + 6 * l + 1];
        adst[l] = (const float*)d_in[8 + 6 * l + 2];
        We[l]   = (const float*)d_in[8 + 6 * l + 3];
        ae[l]   = (const float*)d_in[8 + 6 * l + 4];
        bb[l]   = (const float*)d_in[8 + 6 * l + 5];
    }
    const float* Wlin = (const float*)d_in[26];
    const float* blin = (const float*)d_in[27];
    const float* Wc1  = (const float*)d_in[28];
    const float* bc1  = (const float*)d_in[29];
    const float* Wc2  = (const float*)d_in[30];
    const float* bc2  = (const float*)d_in[31];

    const int eHalfBlocks = (E + 255) / 256;
    const int nT = (N + TILE - 1) / TILE;
    const int tcBlocks = (N + 127) / 128;
    const int g7Blocks = (N + 7) / 8;
    const int aggBlocks = (N * 32 + 255) / 256;

    // fork point
    cudaEventRecord(evF, 0);
    cudaStreamWaitEvent(sCsr, evF, 0);
    cudaStreamWaitEvent(s1, evF, 0);

    // batched CSR build on side stream
    cudaMemsetAsync(b_deg, 0, 2 * MAX_N * sizeof(int), sCsr);
    build_deg_k<<<eHalfBlocks, 256, 0, sCsr>>>(ei[0], ei[1], b_deg, E);
    scan1_k<<<2 * nT, 256, 0, sCsr>>>(b_deg, b_tsum, N, nT);
    scan2_k<<<1, 256, 0, sCsr>>>(b_tsum, nT);
    scan3_k<<<2 * nT, TILE, 0, sCsr>>>(b_deg, b_tsum, b_offs, b_cursor, N, nT);
    scatter_k<<<eHalfBlocks, 256, 0, sCsr>>>(ei[0], ecol[0], ei[1], ecol[1],
                                             b_cursor, b_csre, E);
    cudaEventRecord(evC, sCsr);

    // prologue on stream 0 (graph-invariant)
    cudaMemsetAsync(p_g, 0, 128 * sizeof(float), 0);
    cudaMemsetAsync(b_max, 0, 6 * sizeof(unsigned), 0);
    wsplit_k<<<(128 * 128 + 255) / 256, 256, 0, 0>>>(W[1], b_wfh, b_wfl, 128 * 128);
    wsplit_k<<<(128 * 64 + 255) / 256, 256, 0, 0>>>(W[2], b_wfh + 128 * 128,
                                                    b_wfl + 128 * 128, 128 * 64);
    cscalar3_k<<<1, 96, 0, 0>>>(We[0], ae[0], We[1], ae[1], We[2], ae[2], b_c);
    cudaEventRecord(evP, 0);
    cudaStreamWaitEvent(s1, evP, 0);

    // per-graph chains on two streams
    for (int gph = 0; gph < 2; gph++) {
        cudaStream_t st = gph ? s1 : (cudaStream_t)0;
        __half* p_hh = b_hh + (size_t)gph * MAX_N * 128;
        __half* p_xh = b_xh + (size_t)gph * MAX_N * 128;
        float* p_hs = b_hs + gph * MAX_N;
        float* p_hd = b_hd + gph * MAX_N;
        uint32_t* p_csre = b_csre + (size_t)gph * MAX_E;
        int* p_offs = b_offs + gph * (MAX_N + 1);

        gemm7_k<<<g7Blocks, 256, 0, st>>>(x_in[gph], W[0], asrc[0], adst[0],
                                          p_hh, p_hs, p_hd, b_max + 0 + gph, N);
        cudaStreamWaitEvent(st, evC, 0);

        gat_agg_k<128, false><<<aggBlocks, 256, 0, st>>>(
            p_hh, p_hs, p_hd, p_offs, p_csre, bb[0], b_c + 0,
            b_max + 0 + gph, p_xh, nullptr, N);
        gemm_mma_k<128><<<tcBlocks, 256, 53248, st>>>(
            p_xh, b_wfh, b_wfl, asrc[1], adst[1], p_hh, p_hs, p_hd,
            b_max + 2 + gph, N);
        gat_agg_k<128, false><<<aggBlocks, 256, 0, st>>>(
            p_hh, p_hs, p_hd, p_offs, p_csre, bb[1], b_c + 1,
            b_max + 2 + gph, p_xh, nullptr, N);
        gemm_mma_k<64><<<tcBlocks, 256, 36864, st>>>(
            p_xh, b_wfh + 128 * 128, b_wfl + 128 * 128, asrc[2], adst[2],
            p_hh, p_hs, p_hd, b_max + 4 + gph, N);
        gat_agg_k<64, true><<<aggBlocks, 256, 0, st>>>(
            p_hh, p_hs, p_hd, p_offs, p_csre, bb[2], b_c + 2,
            b_max + 4 + gph, nullptr, p_g + gph * 64, N);
    }

    cudaEventRecord(evJ, s1);
    cudaStreamWaitEvent((cudaStream_t)0, evJ, 0);
    head_k<<<1, 128, 0, 0>>>(p_g, xnorm[0], xnorm[1], Wlin, blin, Wc1, bc1, Wc2, bc2,
                             (float*)d_out, N);
}